// round 7
// baseline (speedup 1.0000x reference)
#include <cuda_runtime.h>
#include <cuda_bf16.h>
#include <cstdint>

// Problem constants (fixed by the reference).
#define NB   4
#define NPTS 50000
#define ND   256
#define NE   800000

// Scratch (static device arrays; no allocation allowed).
__device__ float4 d_x0[NPTS * NB];      // x as [point][batch] float4 (w unused) = 64B/point
__device__ float4 d_x1[NPTS * NB];      // ping-pong buffer
__device__ int    d_cnt[NPTS];          // histogram, then cursor
__device__ int    d_off[NPTS + 1];      // CSR offsets
__device__ int2   d_adj[2 * NE];        // {neighbor point, rest_length as bits}

// ---------------------------------------------------------------------------
// Kernel 1: v_raw = ht @ hw + hb ; x_pred = kp + tau * v_raw  -> d_x0
// Warp-per-row, grid-stride over rows; weights held in registers per lane.
// HBM-bound: streams 204.8 MB of hand_tokens.
// ---------------------------------------------------------------------------
__global__ void k_pred(const float* __restrict__ kp,
                       const float* __restrict__ ts,
                       const float* __restrict__ ht,
                       const float* __restrict__ hw,
                       const float* __restrict__ hb) {
    const int lane = threadIdx.x & 31;
    const int warp = threadIdx.x >> 5;
    const int warps_per_cta = blockDim.x >> 5;

    // Per-lane weight slice: lane covers k = lane*4..+3 and 128+lane*4..+3
    float wr[8][3];
#pragma unroll
    for (int q = 0; q < 8; q++) {
        int k = ((q >> 2) * 128) + lane * 4 + (q & 3);
        wr[q][0] = __ldg(&hw[k * 3 + 0]);
        wr[q][1] = __ldg(&hw[k * 3 + 1]);
        wr[q][2] = __ldg(&hw[k * 3 + 2]);
    }
    const float b0 = __ldg(&hb[0]);
    const float b1 = __ldg(&hb[1]);
    const float b2 = __ldg(&hb[2]);
    float tau_b[NB];
#pragma unroll
    for (int b = 0; b < NB; b++) tau_b[b] = fmaxf(1.0f - __ldg(&ts[b]), 0.001f);

    const int total_rows = NB * NPTS;
    const int row_step = gridDim.x * warps_per_cta;

    for (int row = blockIdx.x * warps_per_cta + warp; row < total_rows; row += row_step) {
        const float* h = ht + (size_t)row * ND;
        float4 va = *reinterpret_cast<const float4*>(h + lane * 4);
        float4 vb = *reinterpret_cast<const float4*>(h + 128 + lane * 4);

        float s0 = va.x * wr[0][0] + va.y * wr[1][0] + va.z * wr[2][0] + va.w * wr[3][0]
                 + vb.x * wr[4][0] + vb.y * wr[5][0] + vb.z * wr[6][0] + vb.w * wr[7][0];
        float s1 = va.x * wr[0][1] + va.y * wr[1][1] + va.z * wr[2][1] + va.w * wr[3][1]
                 + vb.x * wr[4][1] + vb.y * wr[5][1] + vb.z * wr[6][1] + vb.w * wr[7][1];
        float s2 = va.x * wr[0][2] + va.y * wr[1][2] + va.z * wr[2][2] + va.w * wr[3][2]
                 + vb.x * wr[4][2] + vb.y * wr[5][2] + vb.z * wr[6][2] + vb.w * wr[7][2];

#pragma unroll
        for (int o = 16; o > 0; o >>= 1) {
            s0 += __shfl_down_sync(0xffffffffu, s0, o);
            s1 += __shfl_down_sync(0xffffffffu, s1, o);
            s2 += __shfl_down_sync(0xffffffffu, s2, o);
        }

        if (lane == 0) {
            int b = row / NPTS;
            int n = row - b * NPTS;
            float tau = tau_b[b];
            const float* kq = kp + (size_t)row * 3;
            float px = __ldg(&kq[0]) + tau * (s0 + b0);
            float py = __ldg(&kq[1]) + tau * (s1 + b1);
            float pz = __ldg(&kq[2]) + tau * (s2 + b2);
            d_x0[n * NB + b] = make_float4(px, py, pz, 0.0f);
        }
    }
}

// ---------------------------------------------------------------------------
// CSR build: zero -> histogram -> scan (single CTA) -> cursor copy -> fill
// ---------------------------------------------------------------------------
__global__ void k_zero() {
    int i = blockIdx.x * blockDim.x + threadIdx.x;
    if (i < NPTS) d_cnt[i] = 0;
}

__global__ void k_hist(const int* __restrict__ ei) {
    int e = blockIdx.x * blockDim.x + threadIdx.x;
    if (e >= NE) return;
    atomicAdd(&d_cnt[ei[e]], 1);
    atomicAdd(&d_cnt[ei[NE + e]], 1);
}

__global__ void k_scan() {
    __shared__ int wsum[33];
    __shared__ int s_running;
    const int tid = threadIdx.x;      // 1024 threads
    const int lane = tid & 31, wid = tid >> 5;
    if (tid == 0) s_running = 0;
    __syncthreads();

    for (int base = 0; base < NPTS; base += 1024) {
        int i = base + tid;
        int v = (i < NPTS) ? d_cnt[i] : 0;
        int x = v;
#pragma unroll
        for (int d = 1; d < 32; d <<= 1) {
            int t = __shfl_up_sync(0xffffffffu, x, d);
            if (lane >= d) x += t;
        }
        if (lane == 31) wsum[wid] = x;
        __syncthreads();
        if (wid == 0) {
            int w = wsum[lane];
            int y = w;
#pragma unroll
            for (int d = 1; d < 32; d <<= 1) {
                int t = __shfl_up_sync(0xffffffffu, y, d);
                if (lane >= d) y += t;
            }
            wsum[lane] = y - w;           // exclusive warp offsets
            if (lane == 31) wsum[32] = y; // block total
        }
        __syncthreads();
        if (i < NPTS) d_off[i] = s_running + wsum[wid] + (x - v);
        __syncthreads();
        if (tid == 0) s_running += wsum[32];
        __syncthreads();
    }
    if (tid == 0) d_off[NPTS] = s_running;   // == 2*NE
}

__global__ void k_copy() {
    int i = blockIdx.x * blockDim.x + threadIdx.x;
    if (i < NPTS) d_cnt[i] = d_off[i];
}

__global__ void k_fill(const int* __restrict__ ei, const float* __restrict__ rest) {
    int e = blockIdx.x * blockDim.x + threadIdx.x;
    if (e >= NE) return;
    int s = ei[e];
    int d = ei[NE + e];
    int Lb = __float_as_int(rest[e]);
    int p = atomicAdd(&d_cnt[s], 1);
    d_adj[p] = make_int2(d, Lb);
    int q = atomicAdd(&d_cnt[d], 1);
    d_adj[q] = make_int2(s, Lb);
}

// ---------------------------------------------------------------------------
// XPBD Jacobi iteration (gather form, no atomics).
// Thread t handles (point = t>>2, batch = t&3). Groups of 4 lanes fetch the
// same 64B neighbor record as contiguous float4s (sector-perfect).
// Both edge roles reduce to the same formula (clip is odd-symmetric):
//   delta_me += clamp( (L0 - dist)/denom * (x_me - x_nbr)/(dist+1e-9) )
// Self-edges give dx=dy=dz=0 -> contribution exactly 0, matching reference.
// ---------------------------------------------------------------------------
__device__ __forceinline__ float3 solve_point(const float4* __restrict__ xin,
                                              float4 me, int b, int s, int e) {
    float ax = 0.0f, ay = 0.0f, az = 0.0f;
    const float invDenom = 0.5f;   // 1/(w_i+w_j+alpha+1e-9) = 1/(2+1e-9)

#pragma unroll 8
    for (int j = s; j < e; j++) {
        int2 a = __ldg(&d_adj[j]);
        float4 o = xin[(a.x << 2) | b];
        float dx = me.x - o.x;
        float dy = me.y - o.y;
        float dz = me.z - o.z;
        float d2 = dx * dx + dy * dy + dz * dz;
        float dist = sqrtf(d2);
        float L0 = __int_as_float(a.y);
        float scale = (L0 - dist) * invDenom / (dist + 1e-9f);
        ax += fminf(fmaxf(scale * dx, -0.15f), 0.15f);
        ay += fminf(fmaxf(scale * dy, -0.15f), 0.15f);
        az += fminf(fmaxf(scale * dz, -0.15f), 0.15f);
    }
    return make_float3(me.x + ax, me.y + ay, me.z + az);
}

__global__ void __launch_bounds__(256) k_solve(int flip) {
    const float4* __restrict__ xin  = flip ? d_x1 : d_x0;
    float4* __restrict__ xout = flip ? d_x0 : d_x1;

    int t = blockIdx.x * blockDim.x + threadIdx.x;
    if (t >= NPTS * NB) return;
    const int p = t >> 2;
    const int b = t & 3;

    float4 me = xin[t];
    float3 r = solve_point(xin, me, b, d_off[p], d_off[p + 1]);
    xout[t] = make_float4(r.x, r.y, r.z, 0.0f);
}

// Last iteration fused with the epilogue: out = (x_new - keypoints) / tau.
// Input is d_x1 (after 3 iterations x lives in x1); output goes straight to
// gmem in [B][N][3] layout, saving one full pass over x.
__global__ void __launch_bounds__(256) k_solve_final(const float* __restrict__ kp,
                                                     const float* __restrict__ ts,
                                                     float* __restrict__ out) {
    const float4* __restrict__ xin = d_x1;

    int t = blockIdx.x * blockDim.x + threadIdx.x;
    if (t >= NPTS * NB) return;
    const int p = t >> 2;
    const int b = t & 3;

    float4 me = xin[t];
    float3 r = solve_point(xin, me, b, d_off[p], d_off[p + 1]);

    float tau = fmaxf(1.0f - __ldg(&ts[b]), 0.001f);
    float inv = 1.0f / tau;
    const float* kq = kp + ((size_t)b * NPTS + p) * 3;
    float* oq = out + ((size_t)b * NPTS + p) * 3;
    oq[0] = (r.x - __ldg(&kq[0])) * inv;
    oq[1] = (r.y - __ldg(&kq[1])) * inv;
    oq[2] = (r.z - __ldg(&kq[2])) * inv;
}

// ---------------------------------------------------------------------------
// Launch. Input order per metadata: keypoints, timesteps, hand_tokens,
// head_w, head_b, edge_index, rest_lengths. Output: float32 [B][N][3].
// ---------------------------------------------------------------------------
extern "C" void kernel_launch(void* const* d_in, const int* in_sizes, int n_in,
                              void* d_out, int out_size) {
    const float* kp   = (const float*)d_in[0];
    const float* ts   = (const float*)d_in[1];
    const float* ht   = (const float*)d_in[2];
    const float* hw   = (const float*)d_in[3];
    const float* hb   = (const float*)d_in[4];
    const int*   ei   = (const int*)  d_in[5];
    const float* rest = (const float*)d_in[6];
    float* out = (float*)d_out;

    // 1) prediction + head GEMV (HBM-bound, ~205 MB)
    k_pred<<<1184, 256>>>(kp, ts, ht, hw, hb);

    // 2) CSR build
    k_zero<<<(NPTS + 255) / 256, 256>>>();
    k_hist<<<(NE + 255) / 256, 256>>>(ei);
    k_scan<<<1, 1024>>>();
    k_copy<<<(NPTS + 255) / 256, 256>>>();
    k_fill<<<(NE + 255) / 256, 256>>>(ei, rest);

    // 3) 4 XPBD Jacobi iterations (last fused with epilogue)
    const int solveBlocks = (NPTS * NB + 255) / 256;
    k_solve<<<solveBlocks, 256>>>(0);   // x0 -> x1
    k_solve<<<solveBlocks, 256>>>(1);   // x1 -> x0
    k_solve<<<solveBlocks, 256>>>(0);   // x0 -> x1
    k_solve_final<<<solveBlocks, 256>>>(kp, ts, out);  // x1 -> out
}

// round 8
// speedup vs baseline: 1.3832x; 1.3832x over previous
#include <cuda_runtime.h>
#include <cuda_bf16.h>
#include <cstdint>

// Problem constants (fixed by the reference).
#define NB   4
#define NPTS 50000
#define ND   256
#define NE   800000

// Parallel scan geometry.
#define SCAN_T     256
#define SCAN_I     4
#define SCAN_CHUNK (SCAN_T * SCAN_I)                       // 1024 points / CTA
#define NCHUNKS    ((NPTS + SCAN_CHUNK - 1) / SCAN_CHUNK)  // 49

// Scratch (static device arrays; no allocation allowed).
__device__ float4 d_x0[NPTS * NB];      // x as [point][batch] float4 (w unused) = 64B/point
__device__ float4 d_x1[NPTS * NB];      // ping-pong buffer
__device__ int    d_cnt[NPTS];          // histogram, then cursor
__device__ int    d_off[NPTS + 1];      // CSR offsets
__device__ int    d_part[NCHUNKS];      // per-chunk sums -> exclusive chunk offsets
__device__ int2   d_adj[2 * NE];        // {neighbor point, rest_length as bits}

// ---------------------------------------------------------------------------
// Kernel 1: v_raw = ht @ hw + hb ; x_pred = kp + tau * v_raw  -> d_x0
// Warp-per-row, grid-stride; weights in registers. HBM-bound (~205 MB).
// ---------------------------------------------------------------------------
__global__ void k_pred(const float* __restrict__ kp,
                       const float* __restrict__ ts,
                       const float* __restrict__ ht,
                       const float* __restrict__ hw,
                       const float* __restrict__ hb) {
    const int lane = threadIdx.x & 31;
    const int warp = threadIdx.x >> 5;
    const int warps_per_cta = blockDim.x >> 5;

    float wr[8][3];
#pragma unroll
    for (int q = 0; q < 8; q++) {
        int k = ((q >> 2) * 128) + lane * 4 + (q & 3);
        wr[q][0] = __ldg(&hw[k * 3 + 0]);
        wr[q][1] = __ldg(&hw[k * 3 + 1]);
        wr[q][2] = __ldg(&hw[k * 3 + 2]);
    }
    const float b0 = __ldg(&hb[0]);
    const float b1 = __ldg(&hb[1]);
    const float b2 = __ldg(&hb[2]);
    float tau_b[NB];
#pragma unroll
    for (int b = 0; b < NB; b++) tau_b[b] = fmaxf(1.0f - __ldg(&ts[b]), 0.001f);

    const int total_rows = NB * NPTS;
    const int row_step = gridDim.x * warps_per_cta;

    for (int row = blockIdx.x * warps_per_cta + warp; row < total_rows; row += row_step) {
        const float* h = ht + (size_t)row * ND;
        float4 va = *reinterpret_cast<const float4*>(h + lane * 4);
        float4 vb = *reinterpret_cast<const float4*>(h + 128 + lane * 4);

        float s0 = va.x * wr[0][0] + va.y * wr[1][0] + va.z * wr[2][0] + va.w * wr[3][0]
                 + vb.x * wr[4][0] + vb.y * wr[5][0] + vb.z * wr[6][0] + vb.w * wr[7][0];
        float s1 = va.x * wr[0][1] + va.y * wr[1][1] + va.z * wr[2][1] + va.w * wr[3][1]
                 + vb.x * wr[4][1] + vb.y * wr[5][1] + vb.z * wr[6][1] + vb.w * wr[7][1];
        float s2 = va.x * wr[0][2] + va.y * wr[1][2] + va.z * wr[2][2] + va.w * wr[3][2]
                 + vb.x * wr[4][2] + vb.y * wr[5][2] + vb.z * wr[6][2] + vb.w * wr[7][2];

#pragma unroll
        for (int o = 16; o > 0; o >>= 1) {
            s0 += __shfl_down_sync(0xffffffffu, s0, o);
            s1 += __shfl_down_sync(0xffffffffu, s1, o);
            s2 += __shfl_down_sync(0xffffffffu, s2, o);
        }

        if (lane == 0) {
            int b = row / NPTS;
            int n = row - b * NPTS;
            float tau = tau_b[b];
            const float* kq = kp + (size_t)row * 3;
            float px = __ldg(&kq[0]) + tau * (s0 + b0);
            float py = __ldg(&kq[1]) + tau * (s1 + b1);
            float pz = __ldg(&kq[2]) + tau * (s2 + b2);
            d_x0[n * NB + b] = make_float4(px, py, pz, 0.0f);
        }
    }
}

// ---------------------------------------------------------------------------
// CSR build: zero -> histogram -> 3-phase parallel scan -> fill
// ---------------------------------------------------------------------------
__global__ void k_zero() {
    int i = blockIdx.x * blockDim.x + threadIdx.x;
    if (i < NPTS) d_cnt[i] = 0;
}

__global__ void k_hist(const int* __restrict__ ei) {
    int e = blockIdx.x * blockDim.x + threadIdx.x;
    if (e >= NE) return;
    atomicAdd(&d_cnt[ei[e]], 1);
    atomicAdd(&d_cnt[ei[NE + e]], 1);
}

// Phase A: per-chunk sum (49 CTAs x 256 threads x 4 items).
__global__ void k_scanA() {
    __shared__ int ws[SCAN_T / 32];
    int base = blockIdx.x * SCAN_CHUNK + threadIdx.x * SCAN_I;
    int s = 0;
#pragma unroll
    for (int k = 0; k < SCAN_I; k++) {
        int i = base + k;
        if (i < NPTS) s += d_cnt[i];
    }
#pragma unroll
    for (int o = 16; o > 0; o >>= 1) s += __shfl_down_sync(0xffffffffu, s, o);
    if ((threadIdx.x & 31) == 0) ws[threadIdx.x >> 5] = s;
    __syncthreads();
    if (threadIdx.x == 0) {
        int v = 0;
#pragma unroll
        for (int w = 0; w < SCAN_T / 32; w++) v += ws[w];
        d_part[blockIdx.x] = v;
    }
}

// Phase B: one CTA turns the 49 chunk sums into exclusive chunk offsets.
__global__ void k_scanB() {
    __shared__ int s[64];
    int t = threadIdx.x;                 // 64 threads
    int v = (t < NCHUNKS) ? d_part[t] : 0;
    s[t] = v;
    __syncthreads();
#pragma unroll
    for (int o = 1; o < 64; o <<= 1) {
        int add = (t >= o) ? s[t - o] : 0;
        __syncthreads();
        s[t] += add;
        __syncthreads();
    }
    if (t < NCHUNKS) d_part[t] = s[t] - v;     // exclusive
    if (t == 0) d_off[NPTS] = 2 * NE;          // total is a constant
}

// Phase C: per-chunk exclusive scan + chunk offset -> d_off; also seeds the
// fill cursor d_cnt = d_off (fuses the old k_copy).
__global__ void k_scanC() {
    __shared__ int wtot[SCAN_T / 32];
    const int tid = threadIdx.x;
    const int lane = tid & 31, wid = tid >> 5;
    int base = blockIdx.x * SCAN_CHUNK + tid * SCAN_I;

    int v[SCAN_I];
    int s = 0;
#pragma unroll
    for (int k = 0; k < SCAN_I; k++) {
        v[k] = (base + k < NPTS) ? d_cnt[base + k] : 0;
        s += v[k];
    }
    // warp inclusive scan of per-thread sums
    int si = s;
#pragma unroll
    for (int d = 1; d < 32; d <<= 1) {
        int t2 = __shfl_up_sync(0xffffffffu, si, d);
        if (lane >= d) si += t2;
    }
    if (lane == 31) wtot[wid] = si;
    __syncthreads();
    if (tid == 0) {
        int r = 0;
#pragma unroll
        for (int w = 0; w < SCAN_T / 32; w++) { int x = wtot[w]; wtot[w] = r; r += x; }
    }
    __syncthreads();

    int off = d_part[blockIdx.x] + wtot[wid] + (si - s);
#pragma unroll
    for (int k = 0; k < SCAN_I; k++) {
        int i = base + k;
        if (i < NPTS) { d_off[i] = off; d_cnt[i] = off; }
        off += v[k];
    }
}

__global__ void k_fill(const int* __restrict__ ei, const float* __restrict__ rest) {
    int e = blockIdx.x * blockDim.x + threadIdx.x;
    if (e >= NE) return;
    int s = ei[e];
    int d = ei[NE + e];
    int Lb = __float_as_int(rest[e]);
    int p = atomicAdd(&d_cnt[s], 1);
    d_adj[p] = make_int2(d, Lb);
    int q = atomicAdd(&d_cnt[d], 1);
    d_adj[q] = make_int2(s, Lb);
}

// ---------------------------------------------------------------------------
// XPBD Jacobi iteration (gather form, no atomics).
// Thread t handles (point = t>>2, batch = t&3). Groups of 4 lanes fetch the
// same 64B neighbor record as contiguous float4s (sector-perfect).
// Both edge roles reduce to the same formula (clip is odd-symmetric):
//   delta_me += clamp( (L0 - dist)/denom * (x_me - x_nbr)/(dist+1e-9) )
// rsqrt form: inv = rsqrt(max(d2,1e-18)); dist = d2*inv; 1/(dist+1e-9) ~= inv.
// Self-edges: d2=0 -> dist=0, scale finite, scale*dx = 0 (matches reference).
// ---------------------------------------------------------------------------
__device__ __forceinline__ float3 solve_point(const float4* __restrict__ xin,
                                              float4 me, int b, int s, int e) {
    float ax = 0.0f, ay = 0.0f, az = 0.0f;

#pragma unroll 8
    for (int j = s; j < e; j++) {
        int2 a = __ldg(&d_adj[j]);
        float4 o = xin[(a.x << 2) | b];
        float dx = me.x - o.x;
        float dy = me.y - o.y;
        float dz = me.z - o.z;
        float d2 = dx * dx + dy * dy + dz * dz;
        float inv = rsqrtf(fmaxf(d2, 1e-18f));
        float dist = d2 * inv;                       // = sqrt(d2)
        float L0 = __int_as_float(a.y);
        float scale = (L0 - dist) * 0.5f * inv;      // /(dist+1e-9) ~ *inv
        ax += fminf(fmaxf(scale * dx, -0.15f), 0.15f);
        ay += fminf(fmaxf(scale * dy, -0.15f), 0.15f);
        az += fminf(fmaxf(scale * dz, -0.15f), 0.15f);
    }
    return make_float3(me.x + ax, me.y + ay, me.z + az);
}

__global__ void __launch_bounds__(256) k_solve(int flip) {
    const float4* __restrict__ xin  = flip ? d_x1 : d_x0;
    float4* __restrict__ xout = flip ? d_x0 : d_x1;

    int t = blockIdx.x * blockDim.x + threadIdx.x;
    if (t >= NPTS * NB) return;
    const int p = t >> 2;
    const int b = t & 3;

    float4 me = xin[t];
    float3 r = solve_point(xin, me, b, d_off[p], d_off[p + 1]);
    xout[t] = make_float4(r.x, r.y, r.z, 0.0f);
}

// Last iteration fused with the epilogue: out = (x_new - keypoints) / tau.
__global__ void __launch_bounds__(256) k_solve_final(const float* __restrict__ kp,
                                                     const float* __restrict__ ts,
                                                     float* __restrict__ out) {
    const float4* __restrict__ xin = d_x1;

    int t = blockIdx.x * blockDim.x + threadIdx.x;
    if (t >= NPTS * NB) return;
    const int p = t >> 2;
    const int b = t & 3;

    float4 me = xin[t];
    float3 r = solve_point(xin, me, b, d_off[p], d_off[p + 1]);

    float tau = fmaxf(1.0f - __ldg(&ts[b]), 0.001f);
    float inv = 1.0f / tau;
    const float* kq = kp + ((size_t)b * NPTS + p) * 3;
    float* oq = out + ((size_t)b * NPTS + p) * 3;
    oq[0] = (r.x - __ldg(&kq[0])) * inv;
    oq[1] = (r.y - __ldg(&kq[1])) * inv;
    oq[2] = (r.z - __ldg(&kq[2])) * inv;
}

// ---------------------------------------------------------------------------
// Launch. Input order per metadata: keypoints, timesteps, hand_tokens,
// head_w, head_b, edge_index, rest_lengths. Output: float32 [B][N][3].
// ---------------------------------------------------------------------------
extern "C" void kernel_launch(void* const* d_in, const int* in_sizes, int n_in,
                              void* d_out, int out_size) {
    const float* kp   = (const float*)d_in[0];
    const float* ts   = (const float*)d_in[1];
    const float* ht   = (const float*)d_in[2];
    const float* hw   = (const float*)d_in[3];
    const float* hb   = (const float*)d_in[4];
    const int*   ei   = (const int*)  d_in[5];
    const float* rest = (const float*)d_in[6];
    float* out = (float*)d_out;

    // 1) prediction + head GEMV (HBM-bound, ~205 MB)
    k_pred<<<1184, 256>>>(kp, ts, ht, hw, hb);

    // 2) CSR build with parallel scan
    k_zero<<<(NPTS + 255) / 256, 256>>>();
    k_hist<<<(NE + 255) / 256, 256>>>(ei);
    k_scanA<<<NCHUNKS, SCAN_T>>>();
    k_scanB<<<1, 64>>>();
    k_scanC<<<NCHUNKS, SCAN_T>>>();
    k_fill<<<(NE + 255) / 256, 256>>>(ei, rest);

    // 3) 4 XPBD Jacobi iterations (last fused with epilogue)
    const int solveBlocks = (NPTS * NB + 255) / 256;
    k_solve<<<solveBlocks, 256>>>(0);   // x0 -> x1
    k_solve<<<solveBlocks, 256>>>(1);   // x1 -> x0
    k_solve<<<solveBlocks, 256>>>(0);   // x0 -> x1
    k_solve_final<<<solveBlocks, 256>>>(kp, ts, out);  // x1 -> out
}

// round 14
// speedup vs baseline: 1.4204x; 1.0269x over previous
#include <cuda_runtime.h>
#include <cuda_bf16.h>
#include <cstdint>

// Problem constants (fixed by the reference).
#define NB   4
#define NPTS 50000
#define ND   256
#define NE   800000

// Slotted adjacency: degree ~ Binomial(1.6M, 1/50000), mean 32.
// P(deg >= 128) is astronomically small; 128 slots is bulletproof.
#define CAP      128
#define CAP_SHIFT 7

// Scratch (static device arrays; no allocation allowed).
__device__ float4 d_x0[NPTS * NB];      // x as [point][batch] float4 (w unused) = 64B/point
__device__ float4 d_x1[NPTS * NB];      // ping-pong buffer
__device__ int    d_cnt[NPTS];          // fill cursor -> degree
__device__ int2   d_adj[NPTS * CAP];    // {neighbor point, rest_length as bits}

// ---------------------------------------------------------------------------
// Kernel 1: v_raw = ht @ hw + hb ; x_pred = kp + tau * v_raw  -> d_x0
// Warp-per-row, grid-stride; weights in registers. HBM-bound (~205 MB).
// Also zeroes the adjacency cursor (fused former k_zero; runs before k_fill
// by stream ordering).
// ---------------------------------------------------------------------------
__global__ void k_pred(const float* __restrict__ kp,
                       const float* __restrict__ ts,
                       const float* __restrict__ ht,
                       const float* __restrict__ hw,
                       const float* __restrict__ hb) {
    // Fused cursor zeroing: grid has 303k threads >= NPTS.
    {
        int z = blockIdx.x * blockDim.x + threadIdx.x;
        if (z < NPTS) d_cnt[z] = 0;
    }

    const int lane = threadIdx.x & 31;
    const int warp = threadIdx.x >> 5;
    const int warps_per_cta = blockDim.x >> 5;

    float wr[8][3];
#pragma unroll
    for (int q = 0; q < 8; q++) {
        int k = ((q >> 2) * 128) + lane * 4 + (q & 3);
        wr[q][0] = __ldg(&hw[k * 3 + 0]);
        wr[q][1] = __ldg(&hw[k * 3 + 1]);
        wr[q][2] = __ldg(&hw[k * 3 + 2]);
    }
    const float b0 = __ldg(&hb[0]);
    const float b1 = __ldg(&hb[1]);
    const float b2 = __ldg(&hb[2]);
    float tau_b[NB];
#pragma unroll
    for (int b = 0; b < NB; b++) tau_b[b] = fmaxf(1.0f - __ldg(&ts[b]), 0.001f);

    const int total_rows = NB * NPTS;
    const int row_step = gridDim.x * warps_per_cta;

    for (int row = blockIdx.x * warps_per_cta + warp; row < total_rows; row += row_step) {
        const float* h = ht + (size_t)row * ND;
        float4 va = *reinterpret_cast<const float4*>(h + lane * 4);
        float4 vb = *reinterpret_cast<const float4*>(h + 128 + lane * 4);

        float s0 = va.x * wr[0][0] + va.y * wr[1][0] + va.z * wr[2][0] + va.w * wr[3][0]
                 + vb.x * wr[4][0] + vb.y * wr[5][0] + vb.z * wr[6][0] + vb.w * wr[7][0];
        float s1 = va.x * wr[0][1] + va.y * wr[1][1] + va.z * wr[2][1] + va.w * wr[3][1]
                 + vb.x * wr[4][1] + vb.y * wr[5][1] + vb.z * wr[6][1] + vb.w * wr[7][1];
        float s2 = va.x * wr[0][2] + va.y * wr[1][2] + va.z * wr[2][2] + va.w * wr[3][2]
                 + vb.x * wr[4][2] + vb.y * wr[5][2] + vb.z * wr[6][2] + vb.w * wr[7][2];

#pragma unroll
        for (int o = 16; o > 0; o >>= 1) {
            s0 += __shfl_down_sync(0xffffffffu, s0, o);
            s1 += __shfl_down_sync(0xffffffffu, s1, o);
            s2 += __shfl_down_sync(0xffffffffu, s2, o);
        }

        if (lane == 0) {
            int b = row / NPTS;
            int n = row - b * NPTS;
            float tau = tau_b[b];
            const float* kq = kp + (size_t)row * 3;
            float px = __ldg(&kq[0]) + tau * (s0 + b0);
            float py = __ldg(&kq[1]) + tau * (s1 + b1);
            float pz = __ldg(&kq[2]) + tau * (s2 + b2);
            d_x0[n * NB + b] = make_float4(px, py, pz, 0.0f);
        }
    }
}

// ---------------------------------------------------------------------------
// Adjacency fill: slotted, atomic cursor per point. No histogram/scan needed.
// 2 edges per thread, loads batched up front for MLP.
// After this kernel, d_cnt[p] == degree(p).
// ---------------------------------------------------------------------------
__global__ void k_fill(const int* __restrict__ ei, const float* __restrict__ rest) {
    int e0 = (blockIdx.x * blockDim.x + threadIdx.x) * 2;
    if (e0 >= NE) return;
    int e1 = e0 + 1;
    bool has1 = (e1 < NE);

    // Batch independent loads first (MLP).
    int s0 = __ldg(&ei[e0]);
    int d0 = __ldg(&ei[NE + e0]);
    int L0 = __float_as_int(__ldg(&rest[e0]));
    int s1 = 0, d1 = 0, L1 = 0;
    if (has1) {
        s1 = __ldg(&ei[e1]);
        d1 = __ldg(&ei[NE + e1]);
        L1 = __float_as_int(__ldg(&rest[e1]));
    }

    int p;
    p = atomicAdd(&d_cnt[s0], 1);
    d_adj[(s0 << CAP_SHIFT) + p] = make_int2(d0, L0);
    p = atomicAdd(&d_cnt[d0], 1);
    d_adj[(d0 << CAP_SHIFT) + p] = make_int2(s0, L0);
    if (has1) {
        p = atomicAdd(&d_cnt[s1], 1);
        d_adj[(s1 << CAP_SHIFT) + p] = make_int2(d1, L1);
        p = atomicAdd(&d_cnt[d1], 1);
        d_adj[(d1 << CAP_SHIFT) + p] = make_int2(s1, L1);
    }
}

// ---------------------------------------------------------------------------
// XPBD Jacobi iteration (gather form, no atomics).
// Thread t handles (point = t>>2, batch = t&3). Groups of 4 lanes fetch the
// same 64B neighbor record as contiguous float4s (sector-perfect), and
// broadcast-share each adjacency word.
// Both edge roles reduce to the same formula (clip is odd-symmetric):
//   delta_me += clamp( (L0 - dist)/denom * (x_me - x_nbr)/(dist+1e-9) )
// rsqrt form: inv = rsqrt(max(d2,1e-18)); dist = d2*inv; 1/(dist+1e-9) ~= inv.
// Self-edges: d2=0 -> dist=0, scale finite, scale*dx = 0 (matches reference).
// ---------------------------------------------------------------------------
__device__ __forceinline__ float3 solve_point(const float4* __restrict__ xin,
                                              float4 me, int b, int base, int deg) {
    float ax = 0.0f, ay = 0.0f, az = 0.0f;

#pragma unroll 8
    for (int j = 0; j < deg; j++) {
        int2 a = __ldg(&d_adj[base + j]);
        float4 o = xin[(a.x << 2) | b];
        float dx = me.x - o.x;
        float dy = me.y - o.y;
        float dz = me.z - o.z;
        float d2 = dx * dx + dy * dy + dz * dz;
        float inv = rsqrtf(fmaxf(d2, 1e-18f));
        float dist = d2 * inv;                       // = sqrt(d2)
        float L0 = __int_as_float(a.y);
        float scale = (L0 - dist) * 0.5f * inv;      // /(dist+1e-9) ~ *inv
        ax += fminf(fmaxf(scale * dx, -0.15f), 0.15f);
        ay += fminf(fmaxf(scale * dy, -0.15f), 0.15f);
        az += fminf(fmaxf(scale * dz, -0.15f), 0.15f);
    }
    return make_float3(me.x + ax, me.y + ay, me.z + az);
}

__global__ void __launch_bounds__(256) k_solve(int flip) {
    const float4* __restrict__ xin  = flip ? d_x1 : d_x0;
    float4* __restrict__ xout = flip ? d_x0 : d_x1;

    int t = blockIdx.x * blockDim.x + threadIdx.x;
    if (t >= NPTS * NB) return;
    const int p = t >> 2;
    const int b = t & 3;

    float4 me = xin[t];
    float3 r = solve_point(xin, me, b, p << CAP_SHIFT, __ldg(&d_cnt[p]));
    xout[t] = make_float4(r.x, r.y, r.z, 0.0f);
}

// Last iteration fused with the epilogue: out = (x_new - keypoints) / tau.
__global__ void __launch_bounds__(256) k_solve_final(const float* __restrict__ kp,
                                                     const float* __restrict__ ts,
                                                     float* __restrict__ out) {
    const float4* __restrict__ xin = d_x1;

    int t = blockIdx.x * blockDim.x + threadIdx.x;
    if (t >= NPTS * NB) return;
    const int p = t >> 2;
    const int b = t & 3;

    float4 me = xin[t];
    float3 r = solve_point(xin, me, b, p << CAP_SHIFT, __ldg(&d_cnt[p]));

    float tau = fmaxf(1.0f - __ldg(&ts[b]), 0.001f);
    float inv = 1.0f / tau;
    const float* kq = kp + ((size_t)b * NPTS + p) * 3;
    float* oq = out + ((size_t)b * NPTS + p) * 3;
    oq[0] = (r.x - __ldg(&kq[0])) * inv;
    oq[1] = (r.y - __ldg(&kq[1])) * inv;
    oq[2] = (r.z - __ldg(&kq[2])) * inv;
}

// ---------------------------------------------------------------------------
// Launch. Input order per metadata: keypoints, timesteps, hand_tokens,
// head_w, head_b, edge_index, rest_lengths. Output: float32 [B][N][3].
// 6 launches total: pred(+zero), fill, 3x solve, solve_final.
// ---------------------------------------------------------------------------
extern "C" void kernel_launch(void* const* d_in, const int* in_sizes, int n_in,
                              void* d_out, int out_size) {
    const float* kp   = (const float*)d_in[0];
    const float* ts   = (const float*)d_in[1];
    const float* ht   = (const float*)d_in[2];
    const float* hw   = (const float*)d_in[3];
    const float* hb   = (const float*)d_in[4];
    const int*   ei   = (const int*)  d_in[5];
    const float* rest = (const float*)d_in[6];
    float* out = (float*)d_out;

    // 1) prediction + head GEMV (HBM-bound, ~205 MB); zeroes cursor too
    k_pred<<<1184, 256>>>(kp, ts, ht, hw, hb);

    // 2) slotted adjacency fill (no scan needed)
    k_fill<<<(NE / 2 + 255) / 256, 256>>>(ei, rest);

    // 3) 4 XPBD Jacobi iterations (last fused with epilogue)
    const int solveBlocks = (NPTS * NB + 255) / 256;
    k_solve<<<solveBlocks, 256>>>(0);   // x0 -> x1
    k_solve<<<solveBlocks, 256>>>(1);   // x1 -> x0
    k_solve<<<solveBlocks, 256>>>(0);   // x0 -> x1
    k_solve_final<<<solveBlocks, 256>>>(kp, ts, out);  // x1 -> out
}

// round 16
// speedup vs baseline: 1.5262x; 1.0745x over previous
#include <cuda_runtime.h>
#include <cuda_bf16.h>
#include <cstdint>

// Problem constants (fixed by the reference).
#define NB   4
#define NPTS 50000
#define ND   256
#define NE   800000

// Slotted adjacency: degree ~ Binomial(1.6M, 1/50000), mean 32.
// P(deg >= 128) is astronomically small; 128 slots is bulletproof.
#define CAP      128
#define CAP_SHIFT 7

// Scratch (static device arrays; no allocation allowed).
__device__ float4 d_x0[NPTS * NB];        // x as [point][batch] float4 (w unused) = 64B/point
__device__ float4 d_x1[NPTS * NB];        // ping-pong buffer
__device__ int    d_cnt[NPTS];            // fill cursor -> degree
__device__ int4   d_adj4[NPTS * CAP / 2]; // pairs of {neighbor, rest_length bits}; int2-aliased by fill

// ---------------------------------------------------------------------------
// Kernel 1: v_raw = ht @ hw + hb ; x_pred = kp + tau * v_raw  -> d_x0
// Warp-per-row, grid-stride; weights in registers. HBM-bound (~205 MB).
// Also zeroes the adjacency cursor (fused; runs before k_fill by stream order).
// ---------------------------------------------------------------------------
__global__ void k_pred(const float* __restrict__ kp,
                       const float* __restrict__ ts,
                       const float* __restrict__ ht,
                       const float* __restrict__ hw,
                       const float* __restrict__ hb) {
    {
        int z = blockIdx.x * blockDim.x + threadIdx.x;
        if (z < NPTS) d_cnt[z] = 0;
    }

    const int lane = threadIdx.x & 31;
    const int warp = threadIdx.x >> 5;
    const int warps_per_cta = blockDim.x >> 5;

    float wr[8][3];
#pragma unroll
    for (int q = 0; q < 8; q++) {
        int k = ((q >> 2) * 128) + lane * 4 + (q & 3);
        wr[q][0] = __ldg(&hw[k * 3 + 0]);
        wr[q][1] = __ldg(&hw[k * 3 + 1]);
        wr[q][2] = __ldg(&hw[k * 3 + 2]);
    }
    const float b0 = __ldg(&hb[0]);
    const float b1 = __ldg(&hb[1]);
    const float b2 = __ldg(&hb[2]);
    float tau_b[NB];
#pragma unroll
    for (int b = 0; b < NB; b++) tau_b[b] = fmaxf(1.0f - __ldg(&ts[b]), 0.001f);

    const int total_rows = NB * NPTS;
    const int row_step = gridDim.x * warps_per_cta;

    for (int row = blockIdx.x * warps_per_cta + warp; row < total_rows; row += row_step) {
        const float* h = ht + (size_t)row * ND;
        float4 va = *reinterpret_cast<const float4*>(h + lane * 4);
        float4 vb = *reinterpret_cast<const float4*>(h + 128 + lane * 4);

        float s0 = va.x * wr[0][0] + va.y * wr[1][0] + va.z * wr[2][0] + va.w * wr[3][0]
                 + vb.x * wr[4][0] + vb.y * wr[5][0] + vb.z * wr[6][0] + vb.w * wr[7][0];
        float s1 = va.x * wr[0][1] + va.y * wr[1][1] + va.z * wr[2][1] + va.w * wr[3][1]
                 + vb.x * wr[4][1] + vb.y * wr[5][1] + vb.z * wr[6][1] + vb.w * wr[7][1];
        float s2 = va.x * wr[0][2] + va.y * wr[1][2] + va.z * wr[2][2] + va.w * wr[3][2]
                 + vb.x * wr[4][2] + vb.y * wr[5][2] + vb.z * wr[6][2] + vb.w * wr[7][2];

#pragma unroll
        for (int o = 16; o > 0; o >>= 1) {
            s0 += __shfl_down_sync(0xffffffffu, s0, o);
            s1 += __shfl_down_sync(0xffffffffu, s1, o);
            s2 += __shfl_down_sync(0xffffffffu, s2, o);
        }

        if (lane == 0) {
            int b = row / NPTS;
            int n = row - b * NPTS;
            float tau = tau_b[b];
            const float* kq = kp + (size_t)row * 3;
            float px = __ldg(&kq[0]) + tau * (s0 + b0);
            float py = __ldg(&kq[1]) + tau * (s1 + b1);
            float pz = __ldg(&kq[2]) + tau * (s2 + b2);
            d_x0[n * NB + b] = make_float4(px, py, pz, 0.0f);
        }
    }
}

// ---------------------------------------------------------------------------
// Adjacency fill: slotted, atomic cursor per point (writes int2 view of d_adj4).
// 2 edges per thread, loads batched up front for MLP.
// After this kernel, d_cnt[p] == degree(p).
// ---------------------------------------------------------------------------
__global__ void k_fill(const int* __restrict__ ei, const float* __restrict__ rest) {
    int2* adj2 = reinterpret_cast<int2*>(d_adj4);

    int e0 = (blockIdx.x * blockDim.x + threadIdx.x) * 2;
    if (e0 >= NE) return;
    int e1 = e0 + 1;
    bool has1 = (e1 < NE);

    int s0 = __ldg(&ei[e0]);
    int d0 = __ldg(&ei[NE + e0]);
    int L0 = __float_as_int(__ldg(&rest[e0]));
    int s1 = 0, d1 = 0, L1 = 0;
    if (has1) {
        s1 = __ldg(&ei[e1]);
        d1 = __ldg(&ei[NE + e1]);
        L1 = __float_as_int(__ldg(&rest[e1]));
    }

    int p;
    p = atomicAdd(&d_cnt[s0], 1);
    adj2[(s0 << CAP_SHIFT) + p] = make_int2(d0, L0);
    p = atomicAdd(&d_cnt[d0], 1);
    adj2[(d0 << CAP_SHIFT) + p] = make_int2(s0, L0);
    if (has1) {
        p = atomicAdd(&d_cnt[s1], 1);
        adj2[(s1 << CAP_SHIFT) + p] = make_int2(d1, L1);
        p = atomicAdd(&d_cnt[d1], 1);
        adj2[(d1 << CAP_SHIFT) + p] = make_int2(s1, L1);
    }
}

// ---------------------------------------------------------------------------
// XPBD Jacobi iteration (gather form, no atomics), 2 edges per trip.
// Thread t handles (point = t>>2, batch = t&3). One int4 load fetches two
// adjacency entries; the two neighbor gathers are independent chains (2x MLP).
// Both edge roles reduce to the same formula (clip is odd-symmetric):
//   delta_me += clamp( (L0 - dist)/denom * (x_me - x_nbr)/(dist+1e-9) )
// rsqrt form: inv = rsqrt(max(d2,1e-18)); dist = d2*inv; 1/(dist+1e-9) ~= inv.
// Self-edges: d2=0 -> dist=0, scale finite, scale*dx = 0 (matches reference).
// ---------------------------------------------------------------------------
__device__ __forceinline__ float3 solve_point(const float4* __restrict__ xin,
                                              float4 me, int b, int p, int deg) {
    float ax = 0.0f, ay = 0.0f, az = 0.0f;
    const int pair_base = p << (CAP_SHIFT - 1);   // p * 64 int4 pairs
    const int npair = deg >> 1;

#pragma unroll 4
    for (int j = 0; j < npair; j++) {
        int4 a = __ldg(&d_adj4[pair_base + j]);
        float4 o0 = xin[(a.x << 2) | b];
        float4 o1 = xin[(a.z << 2) | b];

        float dx0 = me.x - o0.x, dy0 = me.y - o0.y, dz0 = me.z - o0.z;
        float dx1 = me.x - o1.x, dy1 = me.y - o1.y, dz1 = me.z - o1.z;
        float d20 = dx0 * dx0 + dy0 * dy0 + dz0 * dz0;
        float d21 = dx1 * dx1 + dy1 * dy1 + dz1 * dz1;
        float inv0 = rsqrtf(fmaxf(d20, 1e-18f));
        float inv1 = rsqrtf(fmaxf(d21, 1e-18f));
        float sc0 = (__int_as_float(a.y) - d20 * inv0) * 0.5f * inv0;
        float sc1 = (__int_as_float(a.w) - d21 * inv1) * 0.5f * inv1;

        ax += fminf(fmaxf(sc0 * dx0, -0.15f), 0.15f);
        ay += fminf(fmaxf(sc0 * dy0, -0.15f), 0.15f);
        az += fminf(fmaxf(sc0 * dz0, -0.15f), 0.15f);
        ax += fminf(fmaxf(sc1 * dx1, -0.15f), 0.15f);
        ay += fminf(fmaxf(sc1 * dy1, -0.15f), 0.15f);
        az += fminf(fmaxf(sc1 * dz1, -0.15f), 0.15f);
    }

    if (deg & 1) {
        const int2* adj2 = reinterpret_cast<const int2*>(d_adj4);
        int2 a = __ldg(&adj2[(p << CAP_SHIFT) + deg - 1]);
        float4 o = xin[(a.x << 2) | b];
        float dx = me.x - o.x, dy = me.y - o.y, dz = me.z - o.z;
        float d2 = dx * dx + dy * dy + dz * dz;
        float inv = rsqrtf(fmaxf(d2, 1e-18f));
        float sc = (__int_as_float(a.y) - d2 * inv) * 0.5f * inv;
        ax += fminf(fmaxf(sc * dx, -0.15f), 0.15f);
        ay += fminf(fmaxf(sc * dy, -0.15f), 0.15f);
        az += fminf(fmaxf(sc * dz, -0.15f), 0.15f);
    }
    return make_float3(me.x + ax, me.y + ay, me.z + az);
}

__global__ void __launch_bounds__(256) k_solve(int flip) {
    const float4* __restrict__ xin  = flip ? d_x1 : d_x0;
    float4* __restrict__ xout = flip ? d_x0 : d_x1;

    int t = blockIdx.x * blockDim.x + threadIdx.x;
    if (t >= NPTS * NB) return;
    const int p = t >> 2;
    const int b = t & 3;

    float4 me = xin[t];
    float3 r = solve_point(xin, me, b, p, __ldg(&d_cnt[p]));
    xout[t] = make_float4(r.x, r.y, r.z, 0.0f);
}

// Last iteration fused with the epilogue: out = (x_new - keypoints) / tau.
__global__ void __launch_bounds__(256) k_solve_final(const float* __restrict__ kp,
                                                     const float* __restrict__ ts,
                                                     float* __restrict__ out) {
    const float4* __restrict__ xin = d_x1;

    int t = blockIdx.x * blockDim.x + threadIdx.x;
    if (t >= NPTS * NB) return;
    const int p = t >> 2;
    const int b = t & 3;

    float4 me = xin[t];
    float3 r = solve_point(xin, me, b, p, __ldg(&d_cnt[p]));

    float tau = fmaxf(1.0f - __ldg(&ts[b]), 0.001f);
    float inv = 1.0f / tau;
    const float* kq = kp + ((size_t)b * NPTS + p) * 3;
    float* oq = out + ((size_t)b * NPTS + p) * 3;
    oq[0] = (r.x - __ldg(&kq[0])) * inv;
    oq[1] = (r.y - __ldg(&kq[1])) * inv;
    oq[2] = (r.z - __ldg(&kq[2])) * inv;
}

// ---------------------------------------------------------------------------
// Launch. Input order per metadata: keypoints, timesteps, hand_tokens,
// head_w, head_b, edge_index, rest_lengths. Output: float32 [B][N][3].
// 6 launches total: pred(+zero), fill, 3x solve, solve_final.
// ---------------------------------------------------------------------------
extern "C" void kernel_launch(void* const* d_in, const int* in_sizes, int n_in,
                              void* d_out, int out_size) {
    const float* kp   = (const float*)d_in[0];
    const float* ts   = (const float*)d_in[1];
    const float* ht   = (const float*)d_in[2];
    const float* hw   = (const float*)d_in[3];
    const float* hb   = (const float*)d_in[4];
    const int*   ei   = (const int*)  d_in[5];
    const float* rest = (const float*)d_in[6];
    float* out = (float*)d_out;

    // 1) prediction + head GEMV (HBM-bound, ~205 MB); zeroes cursor too
    k_pred<<<1184, 256>>>(kp, ts, ht, hw, hb);

    // 2) slotted adjacency fill (no scan needed)
    k_fill<<<(NE / 2 + 255) / 256, 256>>>(ei, rest);

    // 3) 4 XPBD Jacobi iterations (last fused with epilogue)
    const int solveBlocks = (NPTS * NB + 255) / 256;
    k_solve<<<solveBlocks, 256>>>(0);   // x0 -> x1
    k_solve<<<solveBlocks, 256>>>(1);   // x1 -> x0
    k_solve<<<solveBlocks, 256>>>(0);   // x0 -> x1
    k_solve_final<<<solveBlocks, 256>>>(kp, ts, out);  // x1 -> out
}